// round 7
// baseline (speedup 1.0000x reference)
#include <cuda_runtime.h>
#include <cuda_bf16.h>
#include <math.h>

#define NNODES 50000
#define NEDGES 1600000
#define NEG_SLOPE 0.2f
#define EPS_F 1e-16f

// ---------------- scratch (device globals; 16B-aligned for vector ld/st) -----
__device__ __align__(16) float g_h1[NNODES * 32];   // layer1 linear output [N,2,16]
__device__ __align__(16) float g_as1[NNODES * 2];   // per-node src logits, layer1
__device__ __align__(16) float g_ad1[NNODES * 2];   // per-node dst logits, layer1
__device__ __align__(16) float g_ew1[NEDGES * 2];   // exp(leaky(e)) per edge, layer1
__device__ __align__(16) float g_den1[NNODES * 2];  // softmax denominators, layer1
__device__ __align__(16) float g_out1[NNODES * 32]; // aggregated layer1 output
__device__ __align__(16) float g_h2[NNODES * 16];   // layer2 linear output
__device__ __align__(16) float g_as2[NNODES];
__device__ __align__(16) float g_ad2[NNODES];
__device__ __align__(16) float g_ew2[NEDGES];
__device__ __align__(16) float g_den2[NNODES];
__device__ __align__(16) float g_out2[NNODES * 16]; // aggregated layer2 output
__device__ __align__(16) float g_ps[NNODES * 16];   // g @ Wm1[:16]
__device__ __align__(16) float g_pd[NNODES * 16];   // g @ Wm1[16:]
__device__ __align__(16) int   g_src[NEDGES];
__device__ __align__(16) int   g_dst[NEDGES];
__device__ int g_is64;                               // edge_index dtype flag

// ---------------- Kd: detect int64 vs int32 edge_index layout ----------------
// int64 layout: words are [lo, hi, lo, hi, ...] with hi == 0 (ids < 50000).
// int32 layout: odd words are random node ids -> almost surely nonzero.
// Reads words [0,2048) — in-bounds under both interpretations (buffer holds
// 3.2M elements of at least 4 bytes each).
__global__ void kd_detect(const int* __restrict__ ei32) {
    if (threadIdx.x == 0 && blockIdx.x == 0) {
        int any = 0;
        #pragma unroll 8
        for (int i = 1; i < 2048; i += 2) any |= ei32[i];
        g_is64 = (any == 0) ? 1 : 0;
    }
}

// ---------------- K0: edge index conversion (dtype-adaptive) ------------------
__global__ void k0_convert(const void* __restrict__ ei) {
    int e = blockIdx.x * blockDim.x + threadIdx.x;
    if (e >= NEDGES) return;
    int s, d;
    if (g_is64) {
        const long long* p = (const long long*)ei;
        s = (int)p[e];
        d = (int)p[NEDGES + e];
    } else {
        const int* p = (const int*)ei;
        s = p[e];
        d = p[NEDGES + e];
    }
    // defensive clamp: decode errors become rel_err, not IMA
    s = min(max(s, 0), NNODES - 1);
    d = min(max(d, 0), NNODES - 1);
    g_src[e] = s;
    g_dst[e] = d;
}

// ---------------- K1: h1 = x @ W1, plus attention logits ---------------------
// 64 rows/block, 128 threads, each thread computes a 4x4 tile.
#define K1_ROWS 64
#define K1_PAD  258   // 258 % 8 == 2 -> conflict-free x loads across row groups

__global__ void k1_gemm(const float* __restrict__ x, const float* __restrict__ W1,
                        const float* __restrict__ att_src1, const float* __restrict__ att_dst1) {
    extern __shared__ float sm[];
    float* ws = sm;                 // 256*32 = 8192 floats
    float* xs = sm + 8192;          // 64 * 258 floats

    const int t = threadIdx.x;      // 0..127
    const int n0 = blockIdx.x * K1_ROWS;

    // load W1 (row-major [k][m]) into smem
    const float4* W4 = (const float4*)W1;
    for (int i = t; i < 2048; i += 128) ((float4*)ws)[i] = W4[i];

    // load x tile (64 rows x 256) into padded smem
    for (int i = t; i < K1_ROWS * 64; i += 128) {
        int r = i >> 6;
        int q = i & 63;            // float4 index within row
        int n = n0 + r;
        float4 v = make_float4(0.f, 0.f, 0.f, 0.f);
        if (n < NNODES) v = ((const float4*)x)[(size_t)n * 64 + q];
        float* d = &xs[r * K1_PAD + (q << 2)];
        d[0] = v.x; d[1] = v.y; d[2] = v.z; d[3] = v.w;
    }
    __syncthreads();

    const int tc = t & 7;           // col group: cols tc*4 .. tc*4+3
    const int tr = t >> 3;          // row group: rows tr*4 .. tr*4+3
    const int c0 = tc * 4;
    const int r0 = tr * 4;

    float acc[4][4] = {};
    #pragma unroll 4
    for (int k = 0; k < 256; k++) {
        float4 w = *(const float4*)&ws[k * 32 + c0];
        #pragma unroll
        for (int i = 0; i < 4; i++) {
            float xv = xs[(r0 + i) * K1_PAD + k];
            acc[i][0] = fmaf(xv, w.x, acc[i][0]);
            acc[i][1] = fmaf(xv, w.y, acc[i][1]);
            acc[i][2] = fmaf(xv, w.z, acc[i][2]);
            acc[i][3] = fmaf(xv, w.w, acc[i][3]);
        }
    }

    // attention logit partials (cols c0..c0+3 all belong to head tc/4)
    float4 sA = ((const float4*)att_src1)[tc];
    float4 dA = ((const float4*)att_dst1)[tc];
    float pas[4], pad_[4];
    #pragma unroll
    for (int i = 0; i < 4; i++) {
        pas[i]  = acc[i][0]*sA.x + acc[i][1]*sA.y + acc[i][2]*sA.z + acc[i][3]*sA.w;
        pad_[i] = acc[i][0]*dA.x + acc[i][1]*dA.y + acc[i][2]*dA.z + acc[i][3]*dA.w;
    }
    // reduce across the 4 col-groups of each head
    #pragma unroll
    for (int off = 1; off <= 2; off <<= 1) {
        #pragma unroll
        for (int i = 0; i < 4; i++) {
            pas[i]  += __shfl_xor_sync(0xFFFFFFFFu, pas[i],  off);
            pad_[i] += __shfl_xor_sync(0xFFFFFFFFu, pad_[i], off);
        }
    }
    if ((tc & 3) == 0) {
        int h = tc >> 2;  // 0 or 1
        #pragma unroll
        for (int i = 0; i < 4; i++) {
            int n = n0 + r0 + i;
            if (n < NNODES) {
                g_as1[n * 2 + h] = pas[i];
                g_ad1[n * 2 + h] = pad_[i];
            }
        }
    }
    // store h1
    #pragma unroll
    for (int i = 0; i < 4; i++) {
        int n = n0 + r0 + i;
        if (n < NNODES)
            *(float4*)&g_h1[n * 32 + c0] = make_float4(acc[i][0], acc[i][1], acc[i][2], acc[i][3]);
    }
}

// ---------------- K2: layer1 edge weights + denominators ---------------------
__global__ void k2_edge1(void) {
    int e = blockIdx.x * blockDim.x + threadIdx.x;
    if (e >= NEDGES) return;
    int s = g_src[e], d = g_dst[e];
    float2 as = *(const float2*)&g_as1[s * 2];
    float2 ad = *(const float2*)&g_ad1[d * 2];
    float v0 = as.x + ad.x; v0 = v0 > 0.f ? v0 : NEG_SLOPE * v0;
    float v1 = as.y + ad.y; v1 = v1 > 0.f ? v1 : NEG_SLOPE * v1;
    float w0 = __expf(v0);
    float w1 = __expf(v1);
    *(float2*)&g_ew1[e * 2] = make_float2(w0, w1);
    atomicAdd(&g_den1[d * 2 + 0], w0);
    atomicAdd(&g_den1[d * 2 + 1], w1);
}

// ---------------- K3: layer1 message aggregation -----------------------------
__global__ void k3_agg1(void) {
    int e = blockIdx.x * blockDim.x + threadIdx.x;
    if (e >= NEDGES) return;
    int s = g_src[e], d = g_dst[e];
    float2 w   = *(const float2*)&g_ew1[e * 2];
    float2 den = *(const float2*)&g_den1[d * 2];
    float a0 = w.x / (den.x + EPS_F);
    float a1 = w.y / (den.y + EPS_F);
    const float4* hs = (const float4*)&g_h1[s * 32];
    float* o = &g_out1[d * 32];
    #pragma unroll
    for (int q = 0; q < 8; q++) {
        float a = (q < 4) ? a0 : a1;
        float4 v = hs[q];
        atomicAdd(&o[q * 4 + 0], a * v.x);
        atomicAdd(&o[q * 4 + 1], a * v.y);
        atomicAdd(&o[q * 4 + 2], a * v.z);
        atomicAdd(&o[q * 4 + 3], a * v.w);
    }
}

// ---------------- K4: elu(out1+b1) @ W2, layer2 logits -----------------------
__global__ void k4_gemm2(const float* __restrict__ b1, const float* __restrict__ W2,
                         const float* __restrict__ att_src2, const float* __restrict__ att_dst2) {
    __shared__ float w2s[512];
    __shared__ float fs[512];
    const int t = threadIdx.x;      // 256 threads, 16 nodes/block
    const int n0 = blockIdx.x * 16;

    for (int i = t; i < 512; i += 256) w2s[i] = W2[i];
    for (int i = t; i < 512; i += 256) {
        size_t lin = (size_t)n0 * 32 + i;
        float v = (lin < (size_t)NNODES * 32) ? (g_out1[lin] + b1[i & 31]) : 0.f;
        fs[i] = v > 0.f ? v : (__expf(v) - 1.f);   // elu
    }
    __syncthreads();

    const int nl = t >> 4, j = t & 15;
    const int n = n0 + nl;
    float acc = 0.f;
    #pragma unroll
    for (int k = 0; k < 32; k++) acc = fmaf(fs[nl * 32 + k], w2s[k * 16 + j], acc);
    if (n < NNODES) g_h2[n * 16 + j] = acc;

    float pa = acc * att_src2[j];
    float pb = acc * att_dst2[j];
    #pragma unroll
    for (int off = 1; off <= 8; off <<= 1) {
        pa += __shfl_xor_sync(0xFFFFFFFFu, pa, off);
        pb += __shfl_xor_sync(0xFFFFFFFFu, pb, off);
    }
    if (j == 0 && n < NNODES) { g_as2[n] = pa; g_ad2[n] = pb; }
}

// ---------------- K5: layer2 edge weights + denominators ---------------------
__global__ void k5_edge2(void) {
    int e = blockIdx.x * blockDim.x + threadIdx.x;
    if (e >= NEDGES) return;
    int s = g_src[e], d = g_dst[e];
    float v = g_as2[s] + g_ad2[d];
    v = v > 0.f ? v : NEG_SLOPE * v;
    float w = __expf(v);
    g_ew2[e] = w;
    atomicAdd(&g_den2[d], w);
}

// ---------------- K6: layer2 message aggregation -----------------------------
__global__ void k6_agg2(void) {
    int e = blockIdx.x * blockDim.x + threadIdx.x;
    if (e >= NEDGES) return;
    int s = g_src[e], d = g_dst[e];
    float a = g_ew2[e] / (g_den2[d] + EPS_F);
    const float4* hs = (const float4*)&g_h2[s * 16];
    float* o = &g_out2[d * 16];
    #pragma unroll
    for (int q = 0; q < 4; q++) {
        float4 v = hs[q];
        atomicAdd(&o[q * 4 + 0], a * v.x);
        atomicAdd(&o[q * 4 + 1], a * v.y);
        atomicAdd(&o[q * 4 + 2], a * v.z);
        atomicAdd(&o[q * 4 + 3], a * v.w);
    }
}

// ---------------- K7a: per-node edge-MLP precompute --------------------------
// ps = (out2+b2) @ Wm1[:16],  pd = (out2+b2) @ Wm1[16:]
__global__ void k7a_pre(const float* __restrict__ b2, const float* __restrict__ Wm1) {
    __shared__ float wm[512];
    __shared__ float gs[256];
    const int t = threadIdx.x;      // 256 threads, 16 nodes/block
    const int n0 = blockIdx.x * 16;
    for (int i = t; i < 512; i += 256) wm[i] = Wm1[i];
    {
        size_t lin = (size_t)n0 * 16 + t;
        gs[t] = (lin < (size_t)NNODES * 16) ? (g_out2[lin] + b2[t & 15]) : 0.f;
    }
    __syncthreads();
    const int nl = t >> 4, j = t & 15;
    const int n = n0 + nl;
    float a = 0.f, b = 0.f;
    #pragma unroll
    for (int i = 0; i < 16; i++) {
        float g = gs[nl * 16 + i];
        a = fmaf(g, wm[i * 16 + j], a);
        b = fmaf(g, wm[(16 + i) * 16 + j], b);
    }
    if (n < NNODES) {
        g_ps[n * 16 + j] = a;
        g_pd[n * 16 + j] = b;
    }
}

// ---------------- K7b: per-edge MLP ------------------------------------------
__global__ void k7b_edge(const float* __restrict__ bm1, const float* __restrict__ Wm2,
                         const float* __restrict__ bm2, float* __restrict__ out) {
    __shared__ float sb1[16], sw2[16], sb2;
    const int t = threadIdx.x;
    if (t < 16) { sb1[t] = bm1[t]; sw2[t] = Wm2[t]; }
    if (t == 0) sb2 = bm2[0];
    __syncthreads();

    int e = blockIdx.x * blockDim.x + t;
    if (e >= NEDGES) return;
    int s = g_src[e], d = g_dst[e];
    const float4* P = (const float4*)&g_ps[s * 16];
    const float4* Q = (const float4*)&g_pd[d * 16];
    float flow = sb2;
    #pragma unroll
    for (int q = 0; q < 4; q++) {
        float4 p = P[q], r = Q[q];
        float h0 = fmaxf(p.x + r.x + sb1[q * 4 + 0], 0.f);
        float h1 = fmaxf(p.y + r.y + sb1[q * 4 + 1], 0.f);
        float h2 = fmaxf(p.z + r.z + sb1[q * 4 + 2], 0.f);
        float h3 = fmaxf(p.w + r.w + sb1[q * 4 + 3], 0.f);
        flow = fmaf(h0, sw2[q * 4 + 0], flow);
        flow = fmaf(h1, sw2[q * 4 + 1], flow);
        flow = fmaf(h2, sw2[q * 4 + 2], flow);
        flow = fmaf(h3, sw2[q * 4 + 3], flow);
    }
    out[e] = fmaxf(flow, 0.f);
}

// ---------------- launcher ----------------------------------------------------
extern "C" void kernel_launch(void* const* d_in, const int* in_sizes, int n_in,
                              void* d_out, int out_size) {
    const float* x        = (const float*)d_in[0];
    const void*  ei       = d_in[1];                 // int32 or int64; detected on device
    const float* W1       = (const float*)d_in[2];
    const float* att_src1 = (const float*)d_in[3];
    const float* att_dst1 = (const float*)d_in[4];
    const float* b1       = (const float*)d_in[5];
    const float* W2       = (const float*)d_in[6];
    const float* att_src2 = (const float*)d_in[7];
    const float* att_dst2 = (const float*)d_in[8];
    const float* b2       = (const float*)d_in[9];
    const float* Wm1      = (const float*)d_in[10];
    const float* bm1      = (const float*)d_in[11];
    const float* Wm2      = (const float*)d_in[12];
    const float* bm2      = (const float*)d_in[13];
    float* out = (float*)d_out;

    // zero accumulators (memset nodes are graph-capturable)
    void* p;
    cudaGetSymbolAddress(&p, g_den1); cudaMemsetAsync(p, 0, (size_t)NNODES * 2 * sizeof(float));
    cudaGetSymbolAddress(&p, g_out1); cudaMemsetAsync(p, 0, (size_t)NNODES * 32 * sizeof(float));
    cudaGetSymbolAddress(&p, g_den2); cudaMemsetAsync(p, 0, (size_t)NNODES * sizeof(float));
    cudaGetSymbolAddress(&p, g_out2); cudaMemsetAsync(p, 0, (size_t)NNODES * 16 * sizeof(float));

    const int smem1 = (8192 + K1_ROWS * K1_PAD) * sizeof(float);
    cudaFuncSetAttribute(k1_gemm, cudaFuncAttributeMaxDynamicSharedMemorySize, smem1);

    const int EB = (NEDGES + 255) / 256;             // 6250
    const int G1 = (NNODES + K1_ROWS - 1) / K1_ROWS; // 782
    const int NB16 = (NNODES + 15) / 16;             // 3125

    kd_detect<<<1, 32>>>((const int*)ei);
    k0_convert<<<EB, 256>>>(ei);
    k1_gemm<<<G1, 128, smem1>>>(x, W1, att_src1, att_dst1);
    k2_edge1<<<EB, 256>>>();
    k3_agg1<<<EB, 256>>>();
    k4_gemm2<<<NB16, 256>>>(b1, W2, att_src2, att_dst2);
    k5_edge2<<<EB, 256>>>();
    k6_agg2<<<EB, 256>>>();
    k7a_pre<<<NB16, 256>>>(b2, Wm1);
    k7b_edge<<<EB, 256>>>(bm1, Wm2, bm2, out);
    (void)in_sizes; (void)n_in; (void)out_size;
}

// round 9
// speedup vs baseline: 1.8026x; 1.8026x over previous
#include <cuda_runtime.h>
#include <cuda_bf16.h>
#include <math.h>

#define NNODES 50000
#define NEDGES 1600000
#define NEG_SLOPE 0.2f
#define EPS_F 1e-16f

// ---------------- scratch (device globals; 16B-aligned for vector ld/st) -----
__device__ __align__(16) float g_h1[NNODES * 32];   // layer1 linear output [N,2,16]
__device__ __align__(16) float g_as1[NNODES * 2];   // per-node src logits, layer1
__device__ __align__(16) float g_ad1[NNODES * 2];   // per-node dst logits, layer1
__device__ __align__(16) float g_den1[NNODES * 2];  // sum of edge weights, layer1
__device__ __align__(16) float g_out1[NNODES * 32]; // UNNORMALIZED aggregate, layer1
__device__ __align__(16) float g_h2[NNODES * 16];   // layer2 linear output
__device__ __align__(16) float g_as2[NNODES];
__device__ __align__(16) float g_ad2[NNODES];
__device__ __align__(16) float g_den2[NNODES];
__device__ __align__(16) float g_out2[NNODES * 16]; // UNNORMALIZED aggregate, layer2
__device__ __align__(16) float g_ps[NNODES * 16];   // g @ Wm1[:16]
__device__ __align__(16) float g_pd[NNODES * 16];   // g @ Wm1[16:]
__device__ __align__(16) int   g_src[NEDGES];
__device__ __align__(16) int   g_dst[NEDGES];
__device__ int g_is64;                               // edge_index dtype flag

// ---------------- vectorized non-returning global reductions -----------------
__device__ __forceinline__ void red_v4(float* a, float x, float y, float z, float w) {
    asm volatile("red.global.add.v4.f32 [%0], {%1,%2,%3,%4};"
                 :: "l"(a), "f"(x), "f"(y), "f"(z), "f"(w) : "memory");
}
__device__ __forceinline__ void red_v2(float* a, float x, float y) {
    asm volatile("red.global.add.v2.f32 [%0], {%1,%2};"
                 :: "l"(a), "f"(x), "f"(y) : "memory");
}
__device__ __forceinline__ void red_f(float* a, float x) {
    asm volatile("red.global.add.f32 [%0], %1;"
                 :: "l"(a), "f"(x) : "memory");
}

// ---------------- Kd: detect int64 vs int32 edge_index layout ----------------
__global__ void kd_detect(const int* __restrict__ ei32) {
    if (threadIdx.x == 0 && blockIdx.x == 0) {
        int any = 0;
        #pragma unroll 8
        for (int i = 1; i < 2048; i += 2) any |= ei32[i];
        g_is64 = (any == 0) ? 1 : 0;
    }
}

// ---------------- K1: h1 = x @ W1, plus attention logits ---------------------
#define K1_ROWS 64
#define K1_PAD  258

__global__ void k1_gemm(const float* __restrict__ x, const float* __restrict__ W1,
                        const float* __restrict__ att_src1, const float* __restrict__ att_dst1) {
    extern __shared__ float sm[];
    float* ws = sm;                 // 256*32 floats
    float* xs = sm + 8192;          // 64 * 258 floats

    const int t = threadIdx.x;      // 0..127
    const int n0 = blockIdx.x * K1_ROWS;

    const float4* W4 = (const float4*)W1;
    for (int i = t; i < 2048; i += 128) ((float4*)ws)[i] = W4[i];

    for (int i = t; i < K1_ROWS * 64; i += 128) {
        int r = i >> 6;
        int q = i & 63;
        int n = n0 + r;
        float4 v = make_float4(0.f, 0.f, 0.f, 0.f);
        if (n < NNODES) v = ((const float4*)x)[(size_t)n * 64 + q];
        float* d = &xs[r * K1_PAD + (q << 2)];
        d[0] = v.x; d[1] = v.y; d[2] = v.z; d[3] = v.w;
    }
    __syncthreads();

    const int tc = t & 7;
    const int tr = t >> 3;
    const int c0 = tc * 4;
    const int r0 = tr * 4;

    float acc[4][4] = {};
    #pragma unroll 4
    for (int k = 0; k < 256; k++) {
        float4 w = *(const float4*)&ws[k * 32 + c0];
        #pragma unroll
        for (int i = 0; i < 4; i++) {
            float xv = xs[(r0 + i) * K1_PAD + k];
            acc[i][0] = fmaf(xv, w.x, acc[i][0]);
            acc[i][1] = fmaf(xv, w.y, acc[i][1]);
            acc[i][2] = fmaf(xv, w.z, acc[i][2]);
            acc[i][3] = fmaf(xv, w.w, acc[i][3]);
        }
    }

    float4 sA = ((const float4*)att_src1)[tc];
    float4 dA = ((const float4*)att_dst1)[tc];
    float pas[4], pad_[4];
    #pragma unroll
    for (int i = 0; i < 4; i++) {
        pas[i]  = acc[i][0]*sA.x + acc[i][1]*sA.y + acc[i][2]*sA.z + acc[i][3]*sA.w;
        pad_[i] = acc[i][0]*dA.x + acc[i][1]*dA.y + acc[i][2]*dA.z + acc[i][3]*dA.w;
    }
    #pragma unroll
    for (int off = 1; off <= 2; off <<= 1) {
        #pragma unroll
        for (int i = 0; i < 4; i++) {
            pas[i]  += __shfl_xor_sync(0xFFFFFFFFu, pas[i],  off);
            pad_[i] += __shfl_xor_sync(0xFFFFFFFFu, pad_[i], off);
        }
    }
    if ((tc & 3) == 0) {
        int h = tc >> 2;
        #pragma unroll
        for (int i = 0; i < 4; i++) {
            int n = n0 + r0 + i;
            if (n < NNODES) {
                g_as1[n * 2 + h] = pas[i];
                g_ad1[n * 2 + h] = pad_[i];
            }
        }
    }
    #pragma unroll
    for (int i = 0; i < 4; i++) {
        int n = n0 + r0 + i;
        if (n < NNODES)
            *(float4*)&g_h1[n * 32 + c0] = make_float4(acc[i][0], acc[i][1], acc[i][2], acc[i][3]);
    }
}

// ---------------- K2: fused index convert + layer1 edge weight + aggregate ----
// One edge pass: decode indices, compute w = exp(leaky(logit)), red-accumulate
// w into den1[d] and w*h1[src] into out1[d]. Normalization deferred to k4.
__global__ void k2_fused(const void* __restrict__ ei) {
    int e = blockIdx.x * blockDim.x + threadIdx.x;
    if (e >= NEDGES) return;
    int s, d;
    if (g_is64) {
        const long long* p = (const long long*)ei;
        s = (int)p[e];
        d = (int)p[NEDGES + e];
    } else {
        const int* p = (const int*)ei;
        s = p[e];
        d = p[NEDGES + e];
    }
    s = min(max(s, 0), NNODES - 1);
    d = min(max(d, 0), NNODES - 1);
    g_src[e] = s;
    g_dst[e] = d;

    float2 as = *(const float2*)&g_as1[s * 2];
    float2 ad = *(const float2*)&g_ad1[d * 2];
    float v0 = as.x + ad.x; v0 = v0 > 0.f ? v0 : NEG_SLOPE * v0;
    float v1 = as.y + ad.y; v1 = v1 > 0.f ? v1 : NEG_SLOPE * v1;
    float w0 = __expf(v0);
    float w1 = __expf(v1);
    red_v2(&g_den1[d * 2], w0, w1);

    const float4* hs = (const float4*)&g_h1[s * 32];
    float* o = &g_out1[d * 32];
    #pragma unroll
    for (int q = 0; q < 8; q++) {
        float a = (q < 4) ? w0 : w1;
        float4 v = hs[q];
        red_v4(o + q * 4, a * v.x, a * v.y, a * v.z, a * v.w);
    }
}

// ---------------- K4: normalize + elu(.+b1) @ W2, layer2 logits --------------
__global__ void k4_gemm2(const float* __restrict__ b1, const float* __restrict__ W2,
                         const float* __restrict__ att_src2, const float* __restrict__ att_dst2) {
    __shared__ float w2s[512];
    __shared__ float fs[512];
    const int t = threadIdx.x;      // 256 threads, 16 nodes/block
    const int n0 = blockIdx.x * 16;

    for (int i = t; i < 512; i += 256) w2s[i] = W2[i];
    for (int i = t; i < 512; i += 256) {
        size_t lin = (size_t)n0 * 32 + i;
        float v = 0.f;
        if (lin < (size_t)NNODES * 32) {
            int node = n0 + (i >> 5);
            int ch = i & 31;
            float den = g_den1[node * 2 + (ch >> 4)] + EPS_F;
            v = g_out1[lin] / den + b1[ch];
        }
        fs[i] = v > 0.f ? v : (__expf(v) - 1.f);   // elu
    }
    __syncthreads();

    const int nl = t >> 4, j = t & 15;
    const int n = n0 + nl;
    float acc = 0.f;
    #pragma unroll
    for (int k = 0; k < 32; k++) acc = fmaf(fs[nl * 32 + k], w2s[k * 16 + j], acc);
    if (n < NNODES) g_h2[n * 16 + j] = acc;

    float pa = acc * att_src2[j];
    float pb = acc * att_dst2[j];
    #pragma unroll
    for (int off = 1; off <= 8; off <<= 1) {
        pa += __shfl_xor_sync(0xFFFFFFFFu, pa, off);
        pb += __shfl_xor_sync(0xFFFFFFFFu, pb, off);
    }
    if (j == 0 && n < NNODES) { g_as2[n] = pa; g_ad2[n] = pb; }
}

// ---------------- K5: fused layer2 edge weight + aggregate -------------------
__global__ void k5_fused(void) {
    int e = blockIdx.x * blockDim.x + threadIdx.x;
    if (e >= NEDGES) return;
    int s = g_src[e], d = g_dst[e];
    float v = g_as2[s] + g_ad2[d];
    v = v > 0.f ? v : NEG_SLOPE * v;
    float w = __expf(v);
    red_f(&g_den2[d], w);
    const float4* hs = (const float4*)&g_h2[s * 16];
    float* o = &g_out2[d * 16];
    #pragma unroll
    for (int q = 0; q < 4; q++) {
        float4 x = hs[q];
        red_v4(o + q * 4, w * x.x, w * x.y, w * x.z, w * x.w);
    }
}

// ---------------- K7a: normalize + per-node edge-MLP precompute --------------
// ps = g @ Wm1[:16], pd = g @ Wm1[16:], where g = out2/den2 + b2
__global__ void k7a_pre(const float* __restrict__ b2, const float* __restrict__ Wm1) {
    __shared__ float wm[512];
    __shared__ float gs[256];
    const int t = threadIdx.x;      // 256 threads, 16 nodes/block
    const int n0 = blockIdx.x * 16;
    for (int i = t; i < 512; i += 256) wm[i] = Wm1[i];
    {
        size_t lin = (size_t)n0 * 16 + t;
        float v = 0.f;
        if (lin < (size_t)NNODES * 16) {
            int node = n0 + (t >> 4);
            float den = g_den2[node] + EPS_F;
            v = g_out2[lin] / den + b2[t & 15];
        }
        gs[t] = v;
    }
    __syncthreads();
    const int nl = t >> 4, j = t & 15;
    const int n = n0 + nl;
    float a = 0.f, b = 0.f;
    #pragma unroll
    for (int i = 0; i < 16; i++) {
        float g = gs[nl * 16 + i];
        a = fmaf(g, wm[i * 16 + j], a);
        b = fmaf(g, wm[(16 + i) * 16 + j], b);
    }
    if (n < NNODES) {
        g_ps[n * 16 + j] = a;
        g_pd[n * 16 + j] = b;
    }
}

// ---------------- K7b: per-edge MLP ------------------------------------------
__global__ void k7b_edge(const float* __restrict__ bm1, const float* __restrict__ Wm2,
                         const float* __restrict__ bm2, float* __restrict__ out) {
    __shared__ float sb1[16], sw2[16], sb2;
    const int t = threadIdx.x;
    if (t < 16) { sb1[t] = bm1[t]; sw2[t] = Wm2[t]; }
    if (t == 0) sb2 = bm2[0];
    __syncthreads();

    int e = blockIdx.x * blockDim.x + t;
    if (e >= NEDGES) return;
    int s = g_src[e], d = g_dst[e];
    const float4* P = (const float4*)&g_ps[s * 16];
    const float4* Q = (const float4*)&g_pd[d * 16];
    float flow = sb2;
    #pragma unroll
    for (int q = 0; q < 4; q++) {
        float4 p = P[q], r = Q[q];
        float h0 = fmaxf(p.x + r.x + sb1[q * 4 + 0], 0.f);
        float h1 = fmaxf(p.y + r.y + sb1[q * 4 + 1], 0.f);
        float h2 = fmaxf(p.z + r.z + sb1[q * 4 + 2], 0.f);
        float h3 = fmaxf(p.w + r.w + sb1[q * 4 + 3], 0.f);
        flow = fmaf(h0, sw2[q * 4 + 0], flow);
        flow = fmaf(h1, sw2[q * 4 + 1], flow);
        flow = fmaf(h2, sw2[q * 4 + 2], flow);
        flow = fmaf(h3, sw2[q * 4 + 3], flow);
    }
    out[e] = fmaxf(flow, 0.f);
}

// ---------------- launcher ----------------------------------------------------
extern "C" void kernel_launch(void* const* d_in, const int* in_sizes, int n_in,
                              void* d_out, int out_size) {
    const float* x        = (const float*)d_in[0];
    const void*  ei       = d_in[1];                 // int32 or int64; detected on device
    const float* W1       = (const float*)d_in[2];
    const float* att_src1 = (const float*)d_in[3];
    const float* att_dst1 = (const float*)d_in[4];
    const float* b1       = (const float*)d_in[5];
    const float* W2       = (const float*)d_in[6];
    const float* att_src2 = (const float*)d_in[7];
    const float* att_dst2 = (const float*)d_in[8];
    const float* b2       = (const float*)d_in[9];
    const float* Wm1      = (const float*)d_in[10];
    const float* bm1      = (const float*)d_in[11];
    const float* Wm2      = (const float*)d_in[12];
    const float* bm2      = (const float*)d_in[13];
    float* out = (float*)d_out;

    // zero accumulators (memset nodes are graph-capturable)
    void* p;
    cudaGetSymbolAddress(&p, g_den1); cudaMemsetAsync(p, 0, (size_t)NNODES * 2 * sizeof(float));
    cudaGetSymbolAddress(&p, g_out1); cudaMemsetAsync(p, 0, (size_t)NNODES * 32 * sizeof(float));
    cudaGetSymbolAddress(&p, g_den2); cudaMemsetAsync(p, 0, (size_t)NNODES * sizeof(float));
    cudaGetSymbolAddress(&p, g_out2); cudaMemsetAsync(p, 0, (size_t)NNODES * 16 * sizeof(float));

    const int smem1 = (8192 + K1_ROWS * K1_PAD) * sizeof(float);
    cudaFuncSetAttribute(k1_gemm, cudaFuncAttributeMaxDynamicSharedMemorySize, smem1);

    const int EB = (NEDGES + 255) / 256;             // 6250
    const int G1 = (NNODES + K1_ROWS - 1) / K1_ROWS; // 782
    const int NB16 = (NNODES + 15) / 16;             // 3125

    kd_detect<<<1, 32>>>((const int*)ei);
    k1_gemm<<<G1, 128, smem1>>>(x, W1, att_src1, att_dst1);
    k2_fused<<<EB, 256>>>(ei);
    k4_gemm2<<<NB16, 256>>>(b1, W2, att_src2, att_dst2);
    k5_fused<<<EB, 256>>>();
    k7a_pre<<<NB16, 256>>>(b2, Wm1);
    k7b_edge<<<EB, 256>>>(bm1, Wm2, bm2, out);
    (void)in_sizes; (void)n_in; (void)out_size;
}

// round 10
// speedup vs baseline: 1.9651x; 1.0902x over previous
#include <cuda_runtime.h>
#include <cuda_bf16.h>
#include <math.h>

#define NNODES 50000
#define NEDGES 1600000
#define NEG_SLOPE 0.2f
#define EPS_F 1e-16f

// ---------------- scratch (device globals) ------------------------------------
__device__ __align__(16) float g_h1[NNODES * 32];   // layer1 linear output [N,2,16]
__device__ __align__(16) float g_as1[NNODES * 2];
__device__ __align__(16) float g_ad1[NNODES * 2];
__device__ __align__(16) float g_out1[NNODES * 32]; // NORMALIZED aggregate, layer1
__device__ __align__(16) float g_h2[NNODES * 16];
__device__ __align__(16) float g_as2[NNODES];
__device__ __align__(16) float g_ad2[NNODES];
__device__ __align__(16) float g_out2[NNODES * 16]; // NORMALIZED aggregate, layer2
__device__ __align__(16) float g_ps[NNODES * 16];
__device__ __align__(16) float g_pd[NNODES * 16];
__device__ __align__(16) int2  g_perm[NEDGES];      // CSR payload: {src, orig_edge}
__device__ __align__(16) int   g_rowptr[NNODES + 1];
__device__ __align__(16) int   g_cnt[NNODES];       // histogram, then scatter cursor
__device__ int g_is64;

// ---------------- Kd: detect int64 vs int32 edge_index layout ----------------
__global__ void kd_detect(const int* __restrict__ ei32) {
    if (threadIdx.x == 0 && blockIdx.x == 0) {
        int any = 0;
        #pragma unroll 8
        for (int i = 1; i < 2048; i += 2) any |= ei32[i];
        g_is64 = (any == 0) ? 1 : 0;
    }
}

__device__ __forceinline__ int dec_idx(const void* ei, int pos) {
    int v;
    if (g_is64) v = (int)((const long long*)ei)[pos];
    else        v = ((const int*)ei)[pos];
    return min(max(v, 0), NNODES - 1);
}

// ---------------- CSR build: histogram -> scan -> scatter ---------------------
__global__ void kc_hist(const void* __restrict__ ei) {
    int e = blockIdx.x * blockDim.x + threadIdx.x;
    if (e >= NEDGES) return;
    int d = dec_idx(ei, NEDGES + e);
    atomicAdd(&g_cnt[d], 1);
}

__global__ void kc_scan(void) {
    __shared__ int sums[1024];
    const int t = threadIdx.x;
    const int CH = 49;                       // 1024*49 = 50176 >= 50000
    int lo = t * CH, hi = min(lo + CH, NNODES);
    int s = 0;
    for (int i = lo; i < hi; i++) s += g_cnt[i];
    sums[t] = s;
    __syncthreads();
    for (int off = 1; off < 1024; off <<= 1) {
        int v = (t >= off) ? sums[t - off] : 0;
        __syncthreads();
        sums[t] += v;
        __syncthreads();
    }
    int run = (t > 0) ? sums[t - 1] : 0;     // exclusive prefix of this chunk
    for (int i = lo; i < hi; i++) {
        int c = g_cnt[i];
        g_rowptr[i] = run;
        g_cnt[i] = run;                      // scatter cursor
        run += c;
    }
    if (t == 1023) g_rowptr[NNODES] = run;
}

__global__ void kc_scatter(const void* __restrict__ ei) {
    int e = blockIdx.x * blockDim.x + threadIdx.x;
    if (e >= NEDGES) return;
    int s = dec_idx(ei, e);
    int d = dec_idx(ei, NEDGES + e);
    int pos = atomicAdd(&g_cnt[d], 1);
    g_perm[pos] = make_int2(s, e);
}

// ---------------- K1: h1 = x @ W1, plus attention logits ---------------------
#define K1_ROWS 64
#define K1_PAD  258

__global__ void k1_gemm(const float* __restrict__ x, const float* __restrict__ W1,
                        const float* __restrict__ att_src1, const float* __restrict__ att_dst1) {
    extern __shared__ float sm[];
    float* ws = sm;                 // 256*32 floats
    float* xs = sm + 8192;          // 64 * 258 floats

    const int t = threadIdx.x;      // 0..127
    const int n0 = blockIdx.x * K1_ROWS;

    const float4* W4 = (const float4*)W1;
    for (int i = t; i < 2048; i += 128) ((float4*)ws)[i] = W4[i];

    for (int i = t; i < K1_ROWS * 64; i += 128) {
        int r = i >> 6;
        int q = i & 63;
        int n = n0 + r;
        float4 v = make_float4(0.f, 0.f, 0.f, 0.f);
        if (n < NNODES) v = ((const float4*)x)[(size_t)n * 64 + q];
        float* d = &xs[r * K1_PAD + (q << 2)];
        d[0] = v.x; d[1] = v.y; d[2] = v.z; d[3] = v.w;
    }
    __syncthreads();

    const int tc = t & 7;
    const int tr = t >> 3;
    const int c0 = tc * 4;
    const int r0 = tr * 4;

    float acc[4][4] = {};
    #pragma unroll 4
    for (int k = 0; k < 256; k++) {
        float4 w = *(const float4*)&ws[k * 32 + c0];
        #pragma unroll
        for (int i = 0; i < 4; i++) {
            float xv = xs[(r0 + i) * K1_PAD + k];
            acc[i][0] = fmaf(xv, w.x, acc[i][0]);
            acc[i][1] = fmaf(xv, w.y, acc[i][1]);
            acc[i][2] = fmaf(xv, w.z, acc[i][2]);
            acc[i][3] = fmaf(xv, w.w, acc[i][3]);
        }
    }

    float4 sA = ((const float4*)att_src1)[tc];
    float4 dA = ((const float4*)att_dst1)[tc];
    float pas[4], pad_[4];
    #pragma unroll
    for (int i = 0; i < 4; i++) {
        pas[i]  = acc[i][0]*sA.x + acc[i][1]*sA.y + acc[i][2]*sA.z + acc[i][3]*sA.w;
        pad_[i] = acc[i][0]*dA.x + acc[i][1]*dA.y + acc[i][2]*dA.z + acc[i][3]*dA.w;
    }
    #pragma unroll
    for (int off = 1; off <= 2; off <<= 1) {
        #pragma unroll
        for (int i = 0; i < 4; i++) {
            pas[i]  += __shfl_xor_sync(0xFFFFFFFFu, pas[i],  off);
            pad_[i] += __shfl_xor_sync(0xFFFFFFFFu, pad_[i], off);
        }
    }
    if ((tc & 3) == 0) {
        int h = tc >> 2;
        #pragma unroll
        for (int i = 0; i < 4; i++) {
            int n = n0 + r0 + i;
            if (n < NNODES) {
                g_as1[n * 2 + h] = pas[i];
                g_ad1[n * 2 + h] = pad_[i];
            }
        }
    }
    #pragma unroll
    for (int i = 0; i < 4; i++) {
        int n = n0 + r0 + i;
        if (n < NNODES)
            *(float4*)&g_h1[n * 32 + c0] = make_float4(acc[i][0], acc[i][1], acc[i][2], acc[i][3]);
    }
}

// ---------------- K2: layer1 gather-aggregate (warp per dst node) -------------
// 4 edges in flight; lane = sub*8 + ch, sub in [0,4) = edge, ch in [0,8) = 16B chunk.
__global__ void k2_csr(void) {
    const int wid  = (blockIdx.x * blockDim.x + threadIdx.x) >> 5;
    const int lane = threadIdx.x & 31;
    if (wid >= NNODES) return;
    const int d   = wid;
    const int beg = g_rowptr[d], end = g_rowptr[d + 1];
    const float2 ad = *(const float2*)&g_ad1[d * 2];
    const int sub = lane >> 3, ch = lane & 7;

    float4 acc = make_float4(0.f, 0.f, 0.f, 0.f);
    float den0 = 0.f, den1 = 0.f;

    for (int base = beg; base < end; base += 4) {
        int s = 0; float w0 = 0.f, w1 = 0.f;
        if (lane < 4 && base + lane < end) {
            int2 pe = g_perm[base + lane];
            s = pe.x;
            float2 as = *(const float2*)&g_as1[s * 2];
            float v0 = as.x + ad.x; v0 = v0 > 0.f ? v0 : NEG_SLOPE * v0;
            float v1 = as.y + ad.y; v1 = v1 > 0.f ? v1 : NEG_SLOPE * v1;
            w0 = __expf(v0); w1 = __expf(v1);
            den0 += w0; den1 += w1;
        }
        int   se  = __shfl_sync(0xFFFFFFFFu, s,  sub);
        float w0e = __shfl_sync(0xFFFFFFFFu, w0, sub);
        float w1e = __shfl_sync(0xFFFFFFFFu, w1, sub);
        float we = (ch < 4) ? w0e : w1e;
        float4 v = *(const float4*)&g_h1[se * 32 + ch * 4];
        acc.x = fmaf(we, v.x, acc.x);
        acc.y = fmaf(we, v.y, acc.y);
        acc.z = fmaf(we, v.z, acc.z);
        acc.w = fmaf(we, v.w, acc.w);
    }
    // den totals (lanes 0-3 closed under xor 1,2)
    den0 += __shfl_xor_sync(0xFFFFFFFFu, den0, 1);
    den0 += __shfl_xor_sync(0xFFFFFFFFu, den0, 2);
    den1 += __shfl_xor_sync(0xFFFFFFFFu, den1, 1);
    den1 += __shfl_xor_sync(0xFFFFFFFFu, den1, 2);
    den0 = __shfl_sync(0xFFFFFFFFu, den0, 0);
    den1 = __shfl_sync(0xFFFFFFFFu, den1, 0);
    // sum acc across the 4 subs (lanes ch, ch+8, ch+16, ch+24)
    #pragma unroll
    for (int off = 8; off <= 16; off <<= 1) {
        acc.x += __shfl_xor_sync(0xFFFFFFFFu, acc.x, off);
        acc.y += __shfl_xor_sync(0xFFFFFFFFu, acc.y, off);
        acc.z += __shfl_xor_sync(0xFFFFFFFFu, acc.z, off);
        acc.w += __shfl_xor_sync(0xFFFFFFFFu, acc.w, off);
    }
    if (lane < 8) {
        float dn = ((lane < 4) ? den0 : den1) + EPS_F;
        float inv = 1.f / dn;
        *(float4*)&g_out1[d * 32 + lane * 4] =
            make_float4(acc.x * inv, acc.y * inv, acc.z * inv, acc.w * inv);
    }
}

// ---------------- K4: elu(out1+b1) @ W2, layer2 logits -----------------------
__global__ void k4_gemm2(const float* __restrict__ b1, const float* __restrict__ W2,
                         const float* __restrict__ att_src2, const float* __restrict__ att_dst2) {
    __shared__ float w2s[512];
    __shared__ float fs[512];
    const int t = threadIdx.x;      // 256 threads, 16 nodes/block
    const int n0 = blockIdx.x * 16;

    for (int i = t; i < 512; i += 256) w2s[i] = W2[i];
    for (int i = t; i < 512; i += 256) {
        size_t lin = (size_t)n0 * 32 + i;
        float v = (lin < (size_t)NNODES * 32) ? (g_out1[lin] + b1[i & 31]) : 0.f;
        fs[i] = v > 0.f ? v : (__expf(v) - 1.f);   // elu
    }
    __syncthreads();

    const int nl = t >> 4, j = t & 15;
    const int n = n0 + nl;
    float acc = 0.f;
    #pragma unroll
    for (int k = 0; k < 32; k++) acc = fmaf(fs[nl * 32 + k], w2s[k * 16 + j], acc);
    if (n < NNODES) g_h2[n * 16 + j] = acc;

    float pa = acc * att_src2[j];
    float pb = acc * att_dst2[j];
    #pragma unroll
    for (int off = 1; off <= 8; off <<= 1) {
        pa += __shfl_xor_sync(0xFFFFFFFFu, pa, off);
        pb += __shfl_xor_sync(0xFFFFFFFFu, pb, off);
    }
    if (j == 0 && n < NNODES) { g_as2[n] = pa; g_ad2[n] = pb; }
}

// ---------------- K5: layer2 gather-aggregate (warp per dst node) -------------
// 8 edges in flight; lane = sub*4 + ch, sub in [0,8) = edge, ch in [0,4) = 16B chunk.
__global__ void k5_csr(void) {
    const int wid  = (blockIdx.x * blockDim.x + threadIdx.x) >> 5;
    const int lane = threadIdx.x & 31;
    if (wid >= NNODES) return;
    const int d   = wid;
    const int beg = g_rowptr[d], end = g_rowptr[d + 1];
    const float ad = g_ad2[d];
    const int sub = lane >> 2, ch = lane & 3;

    float4 acc = make_float4(0.f, 0.f, 0.f, 0.f);
    float den = 0.f;

    for (int base = beg; base < end; base += 8) {
        int s = 0; float w = 0.f;
        if (lane < 8 && base + lane < end) {
            int2 pe = g_perm[base + lane];
            s = pe.x;
            float v = g_as2[s] + ad;
            v = v > 0.f ? v : NEG_SLOPE * v;
            w = __expf(v);
            den += w;
        }
        int   se = __shfl_sync(0xFFFFFFFFu, s, sub);
        float we = __shfl_sync(0xFFFFFFFFu, w, sub);
        float4 v = *(const float4*)&g_h2[se * 16 + ch * 4];
        acc.x = fmaf(we, v.x, acc.x);
        acc.y = fmaf(we, v.y, acc.y);
        acc.z = fmaf(we, v.z, acc.z);
        acc.w = fmaf(we, v.w, acc.w);
    }
    // den total over lanes 0-7 (closed under xor 1,2,4)
    den += __shfl_xor_sync(0xFFFFFFFFu, den, 1);
    den += __shfl_xor_sync(0xFFFFFFFFu, den, 2);
    den += __shfl_xor_sync(0xFFFFFFFFu, den, 4);
    den = __shfl_sync(0xFFFFFFFFu, den, 0);
    // sum acc across the 8 subs (lanes ch, ch+4, ..., ch+28)
    #pragma unroll
    for (int off = 4; off <= 16; off <<= 1) {
        acc.x += __shfl_xor_sync(0xFFFFFFFFu, acc.x, off);
        acc.y += __shfl_xor_sync(0xFFFFFFFFu, acc.y, off);
        acc.z += __shfl_xor_sync(0xFFFFFFFFu, acc.z, off);
        acc.w += __shfl_xor_sync(0xFFFFFFFFu, acc.w, off);
    }
    if (lane < 4) {
        float inv = 1.f / (den + EPS_F);
        *(float4*)&g_out2[d * 16 + lane * 4] =
            make_float4(acc.x * inv, acc.y * inv, acc.z * inv, acc.w * inv);
    }
}

// ---------------- K7a: per-node edge-MLP precompute --------------------------
__global__ void k7a_pre(const float* __restrict__ b2, const float* __restrict__ Wm1) {
    __shared__ float wm[512];
    __shared__ float gs[256];
    const int t = threadIdx.x;      // 256 threads, 16 nodes/block
    const int n0 = blockIdx.x * 16;
    for (int i = t; i < 512; i += 256) wm[i] = Wm1[i];
    {
        size_t lin = (size_t)n0 * 16 + t;
        gs[t] = (lin < (size_t)NNODES * 16) ? (g_out2[lin] + b2[t & 15]) : 0.f;
    }
    __syncthreads();
    const int nl = t >> 4, j = t & 15;
    const int n = n0 + nl;
    float a = 0.f, b = 0.f;
    #pragma unroll
    for (int i = 0; i < 16; i++) {
        float g = gs[nl * 16 + i];
        a = fmaf(g, wm[i * 16 + j], a);
        b = fmaf(g, wm[(16 + i) * 16 + j], b);
    }
    if (n < NNODES) {
        g_ps[n * 16 + j] = a;
        g_pd[n * 16 + j] = b;
    }
}

// ---------------- K7b: per-edge MLP via CSR (warp per dst node) ---------------
// 8 edges in flight; lane = sub*4 + ch. pd[d]+bm1 loaded once per node.
__global__ void k7b_csr(const float* __restrict__ bm1, const float* __restrict__ Wm2,
                        const float* __restrict__ bm2, float* __restrict__ out) {
    const int wid  = (blockIdx.x * blockDim.x + threadIdx.x) >> 5;
    const int lane = threadIdx.x & 31;
    if (wid >= NNODES) return;
    const int d   = wid;
    const int beg = g_rowptr[d], end = g_rowptr[d + 1];
    const int sub = lane >> 2, ch = lane & 3;

    float4 pdc = *(const float4*)&g_pd[d * 16 + ch * 4];
    float4 b1c = *(const float4*)&bm1[ch * 4];
    pdc.x += b1c.x; pdc.y += b1c.y; pdc.z += b1c.z; pdc.w += b1c.w;
    float4 w2c = *(const float4*)&Wm2[ch * 4];
    float  bb2 = bm2[0];

    for (int base = beg; base < end; base += 8) {
        int s = 0, orig = 0;
        if (lane < 8 && base + lane < end) {
            int2 pe = g_perm[base + lane];
            s = pe.x; orig = pe.y;
        }
        int se = __shfl_sync(0xFFFFFFFFu, s,    sub);
        int oe = __shfl_sync(0xFFFFFFFFu, orig, sub);
        float4 p = *(const float4*)&g_ps[se * 16 + ch * 4];
        float h0 = fmaxf(p.x + pdc.x, 0.f);
        float h1 = fmaxf(p.y + pdc.y, 0.f);
        float h2 = fmaxf(p.z + pdc.z, 0.f);
        float h3 = fmaxf(p.w + pdc.w, 0.f);
        float part = h0 * w2c.x + h1 * w2c.y + h2 * w2c.z + h3 * w2c.w;
        part += __shfl_xor_sync(0xFFFFFFFFu, part, 1);
        part += __shfl_xor_sync(0xFFFFFFFFu, part, 2);
        if (ch == 0 && base + sub < end)
            out[oe] = fmaxf(part + bb2, 0.f);
    }
}

// ---------------- launcher ----------------------------------------------------
extern "C" void kernel_launch(void* const* d_in, const int* in_sizes, int n_in,
                              void* d_out, int out_size) {
    const float* x        = (const float*)d_in[0];
    const void*  ei       = d_in[1];
    const float* W1       = (const float*)d_in[2];
    const float* att_src1 = (const float*)d_in[3];
    const float* att_dst1 = (const float*)d_in[4];
    const float* b1       = (const float*)d_in[5];
    const float* W2       = (const float*)d_in[6];
    const float* att_src2 = (const float*)d_in[7];
    const float* att_dst2 = (const float*)d_in[8];
    const float* b2       = (const float*)d_in[9];
    const float* Wm1      = (const float*)d_in[10];
    const float* bm1      = (const float*)d_in[11];
    const float* Wm2      = (const float*)d_in[12];
    const float* bm2      = (const float*)d_in[13];
    float* out = (float*)d_out;

    void* p;
    cudaGetSymbolAddress(&p, g_cnt);
    cudaMemsetAsync(p, 0, (size_t)NNODES * sizeof(int));

    const int smem1 = (8192 + K1_ROWS * K1_PAD) * sizeof(float);
    cudaFuncSetAttribute(k1_gemm, cudaFuncAttributeMaxDynamicSharedMemorySize, smem1);

    const int EB   = (NEDGES + 255) / 256;             // 6250
    const int G1   = (NNODES + K1_ROWS - 1) / K1_ROWS; // 782
    const int NB16 = (NNODES + 15) / 16;               // 3125
    const int NW   = (NNODES * 32 + 255) / 256;        // 6250 (warp-per-node grids)

    kd_detect<<<1, 32>>>((const int*)ei);
    kc_hist<<<EB, 256>>>(ei);
    kc_scan<<<1, 1024>>>();
    kc_scatter<<<EB, 256>>>(ei);
    k1_gemm<<<G1, 128, smem1>>>(x, W1, att_src1, att_dst1);
    k2_csr<<<NW, 256>>>();
    k4_gemm2<<<NB16, 256>>>(b1, W2, att_src2, att_dst2);
    k5_csr<<<NW, 256>>>();
    k7a_pre<<<NB16, 256>>>(b2, Wm1);
    k7b_csr<<<NW, 256>>>(bm1, Wm2, bm2, out);
    (void)in_sizes; (void)n_in; (void)out_size;
}

// round 11
// speedup vs baseline: 2.0838x; 1.0604x over previous
#include <cuda_runtime.h>
#include <cuda_bf16.h>
#include <math.h>

#define NNODES 50000
#define NEDGES 1600000
#define NEG_SLOPE 0.2f
#define EPS_F 1e-16f

// ---------------- scratch (device globals) ------------------------------------
__device__ __align__(16) float g_h1[NNODES * 32];   // layer1 linear output [N,2,16]
__device__ __align__(16) float g_as1[NNODES * 2];
__device__ __align__(16) float g_ad1[NNODES * 2];
__device__ __align__(16) float g_out1[NNODES * 32]; // NORMALIZED aggregate, layer1
__device__ __align__(16) float g_h2[NNODES * 16];
__device__ __align__(16) float g_as2[NNODES];
__device__ __align__(16) float g_ad2[NNODES];
__device__ __align__(16) float g_ps[NNODES * 16];
__device__ __align__(16) float g_pd[NNODES * 16];
__device__ __align__(16) int2  g_perm[NEDGES];      // CSR payload: {src, orig_edge}
__device__ __align__(16) int   g_rowptr[NNODES + 1];
__device__ __align__(16) int   g_cnt[NNODES];       // histogram, then scatter cursor
__device__ int g_is64;

// ---------------- Kd: detect int64 vs int32 edge_index layout ----------------
__global__ void kd_detect(const int* __restrict__ ei32) {
    if (threadIdx.x == 0 && blockIdx.x == 0) {
        int any = 0;
        #pragma unroll 8
        for (int i = 1; i < 2048; i += 2) any |= ei32[i];
        g_is64 = (any == 0) ? 1 : 0;
    }
}

__device__ __forceinline__ int dec_idx(const void* ei, int pos) {
    int v;
    if (g_is64) v = (int)((const long long*)ei)[pos];
    else        v = ((const int*)ei)[pos];
    return min(max(v, 0), NNODES - 1);
}

// ---------------- CSR build: histogram -> scan -> scatter ---------------------
__global__ void kc_hist(const void* __restrict__ ei) {
    int e = blockIdx.x * blockDim.x + threadIdx.x;
    if (e >= NEDGES) return;
    int d = dec_idx(ei, NEDGES + e);
    atomicAdd(&g_cnt[d], 1);
}

__global__ void kc_scan(void) {
    __shared__ int sums[1024];
    const int t = threadIdx.x;
    const int CH = 49;                       // 1024*49 = 50176 >= 50000
    int lo = t * CH, hi = min(lo + CH, NNODES);
    int s = 0;
    for (int i = lo; i < hi; i++) s += g_cnt[i];
    sums[t] = s;
    __syncthreads();
    for (int off = 1; off < 1024; off <<= 1) {
        int v = (t >= off) ? sums[t - off] : 0;
        __syncthreads();
        sums[t] += v;
        __syncthreads();
    }
    int run = (t > 0) ? sums[t - 1] : 0;
    for (int i = lo; i < hi; i++) {
        int c = g_cnt[i];
        g_rowptr[i] = run;
        g_cnt[i] = run;                      // scatter cursor
        run += c;
    }
    if (t == 1023) g_rowptr[NNODES] = run;
}

__global__ void kc_scatter(const void* __restrict__ ei) {
    int e = blockIdx.x * blockDim.x + threadIdx.x;
    if (e >= NEDGES) return;
    int s = dec_idx(ei, e);
    int d = dec_idx(ei, NEDGES + e);
    int pos = atomicAdd(&g_cnt[d], 1);
    g_perm[pos] = make_int2(s, e);
}

// ---------------- K1: h1 = x @ W1, plus attention logits ---------------------
#define K1_ROWS 64
#define K1_PAD  258

__global__ void k1_gemm(const float* __restrict__ x, const float* __restrict__ W1,
                        const float* __restrict__ att_src1, const float* __restrict__ att_dst1) {
    extern __shared__ float sm[];
    float* ws = sm;                 // 256*32 floats
    float* xs = sm + 8192;          // 64 * 258 floats

    const int t = threadIdx.x;      // 0..127
    const int n0 = blockIdx.x * K1_ROWS;

    const float4* W4 = (const float4*)W1;
    for (int i = t; i < 2048; i += 128) ((float4*)ws)[i] = W4[i];

    for (int i = t; i < K1_ROWS * 64; i += 128) {
        int r = i >> 6;
        int q = i & 63;
        int n = n0 + r;
        float4 v = make_float4(0.f, 0.f, 0.f, 0.f);
        if (n < NNODES) v = ((const float4*)x)[(size_t)n * 64 + q];
        float* d = &xs[r * K1_PAD + (q << 2)];
        d[0] = v.x; d[1] = v.y; d[2] = v.z; d[3] = v.w;
    }
    __syncthreads();

    const int tc = t & 7;
    const int tr = t >> 3;
    const int c0 = tc * 4;
    const int r0 = tr * 4;

    float acc[4][4] = {};
    #pragma unroll 4
    for (int k = 0; k < 256; k++) {
        float4 w = *(const float4*)&ws[k * 32 + c0];
        #pragma unroll
        for (int i = 0; i < 4; i++) {
            float xv = xs[(r0 + i) * K1_PAD + k];
            acc[i][0] = fmaf(xv, w.x, acc[i][0]);
            acc[i][1] = fmaf(xv, w.y, acc[i][1]);
            acc[i][2] = fmaf(xv, w.z, acc[i][2]);
            acc[i][3] = fmaf(xv, w.w, acc[i][3]);
        }
    }

    float4 sA = ((const float4*)att_src1)[tc];
    float4 dA = ((const float4*)att_dst1)[tc];
    float pas[4], pad_[4];
    #pragma unroll
    for (int i = 0; i < 4; i++) {
        pas[i]  = acc[i][0]*sA.x + acc[i][1]*sA.y + acc[i][2]*sA.z + acc[i][3]*sA.w;
        pad_[i] = acc[i][0]*dA.x + acc[i][1]*dA.y + acc[i][2]*dA.z + acc[i][3]*dA.w;
    }
    #pragma unroll
    for (int off = 1; off <= 2; off <<= 1) {
        #pragma unroll
        for (int i = 0; i < 4; i++) {
            pas[i]  += __shfl_xor_sync(0xFFFFFFFFu, pas[i],  off);
            pad_[i] += __shfl_xor_sync(0xFFFFFFFFu, pad_[i], off);
        }
    }
    if ((tc & 3) == 0) {
        int h = tc >> 2;
        #pragma unroll
        for (int i = 0; i < 4; i++) {
            int n = n0 + r0 + i;
            if (n < NNODES) {
                g_as1[n * 2 + h] = pas[i];
                g_ad1[n * 2 + h] = pad_[i];
            }
        }
    }
    #pragma unroll
    for (int i = 0; i < 4; i++) {
        int n = n0 + r0 + i;
        if (n < NNODES)
            *(float4*)&g_h1[n * 32 + c0] = make_float4(acc[i][0], acc[i][1], acc[i][2], acc[i][3]);
    }
}

// ---------------- K2: layer1 gather-aggregate (warp per dst node) -------------
// 8-edge batches, prefetched; gather rounds: 4 edges x 8 chunks of 16B.
__global__ void k2_csr(void) {
    const int wid  = (blockIdx.x * blockDim.x + threadIdx.x) >> 5;
    const int lane = threadIdx.x & 31;
    if (wid >= NNODES) return;
    const int d   = wid;
    const int beg = g_rowptr[d], end = g_rowptr[d + 1];
    const float2 ad = *(const float2*)&g_ad1[d * 2];
    const int sub = lane >> 3, ch = lane & 7;

    float4 acc = make_float4(0.f, 0.f, 0.f, 0.f);
    float den0 = 0.f, den1 = 0.f;

    // prefetch batch 0 (lanes 0-7 own one edge each)
    bool actp = (lane < 8) && (beg + lane < end);
    int sp = actp ? g_perm[beg + lane].x : 0;
    float2 asp = actp ? *(const float2*)&g_as1[sp * 2] : make_float2(0.f, 0.f);

    for (int base = beg; base < end; base += 8) {
        const int  scur = sp;
        const float2 ascur = asp;
        const bool act = actp;
        // prefetch next batch's perm
        int nb = base + 8;
        actp = (lane < 8) && (nb + lane < end);
        sp = actp ? g_perm[nb + lane].x : 0;

        // weights for current batch
        float w0 = 0.f, w1 = 0.f;
        if (act) {
            float v0 = ascur.x + ad.x; v0 = v0 > 0.f ? v0 : NEG_SLOPE * v0;
            float v1 = ascur.y + ad.y; v1 = v1 > 0.f ? v1 : NEG_SLOPE * v1;
            w0 = __expf(v0); w1 = __expf(v1);
            den0 += w0; den1 += w1;
        }
        // two gather rounds of 4 edges each
        #pragma unroll
        for (int r = 0; r < 2; r++) {
            int lsrc = r * 4 + sub;
            int   se  = __shfl_sync(0xFFFFFFFFu, scur, lsrc);
            float w0e = __shfl_sync(0xFFFFFFFFu, w0,   lsrc);
            float w1e = __shfl_sync(0xFFFFFFFFu, w1,   lsrc);
            float we = (ch < 4) ? w0e : w1e;
            float4 v = *(const float4*)&g_h1[se * 32 + ch * 4];
            acc.x = fmaf(we, v.x, acc.x);
            acc.y = fmaf(we, v.y, acc.y);
            acc.z = fmaf(we, v.z, acc.z);
            acc.w = fmaf(we, v.w, acc.w);
        }
        // prefetch next batch's src logits (overlaps loop backedge)
        asp = actp ? *(const float2*)&g_as1[sp * 2] : make_float2(0.f, 0.f);
    }
    // den totals over lanes 0-7
    den0 += __shfl_xor_sync(0xFFFFFFFFu, den0, 1);
    den0 += __shfl_xor_sync(0xFFFFFFFFu, den0, 2);
    den0 += __shfl_xor_sync(0xFFFFFFFFu, den0, 4);
    den1 += __shfl_xor_sync(0xFFFFFFFFu, den1, 1);
    den1 += __shfl_xor_sync(0xFFFFFFFFu, den1, 2);
    den1 += __shfl_xor_sync(0xFFFFFFFFu, den1, 4);
    den0 = __shfl_sync(0xFFFFFFFFu, den0, 0);
    den1 = __shfl_sync(0xFFFFFFFFu, den1, 0);
    // sum acc across the 4 subs (lanes ch, ch+8, ch+16, ch+24)
    #pragma unroll
    for (int off = 8; off <= 16; off <<= 1) {
        acc.x += __shfl_xor_sync(0xFFFFFFFFu, acc.x, off);
        acc.y += __shfl_xor_sync(0xFFFFFFFFu, acc.y, off);
        acc.z += __shfl_xor_sync(0xFFFFFFFFu, acc.z, off);
        acc.w += __shfl_xor_sync(0xFFFFFFFFu, acc.w, off);
    }
    if (lane < 8) {
        float dn = ((lane < 4) ? den0 : den1) + EPS_F;
        float inv = 1.f / dn;
        *(float4*)&g_out1[d * 32 + lane * 4] =
            make_float4(acc.x * inv, acc.y * inv, acc.z * inv, acc.w * inv);
    }
}

// ---------------- K4: elu(out1+b1) @ W2, layer2 logits -----------------------
__global__ void k4_gemm2(const float* __restrict__ b1, const float* __restrict__ W2,
                         const float* __restrict__ att_src2, const float* __restrict__ att_dst2) {
    __shared__ float w2s[512];
    __shared__ float fs[512];
    const int t = threadIdx.x;      // 256 threads, 16 nodes/block
    const int n0 = blockIdx.x * 16;

    for (int i = t; i < 512; i += 256) w2s[i] = W2[i];
    for (int i = t; i < 512; i += 256) {
        size_t lin = (size_t)n0 * 32 + i;
        float v = (lin < (size_t)NNODES * 32) ? (g_out1[lin] + b1[i & 31]) : 0.f;
        fs[i] = v > 0.f ? v : (__expf(v) - 1.f);   // elu
    }
    __syncthreads();

    const int nl = t >> 4, j = t & 15;
    const int n = n0 + nl;
    float acc = 0.f;
    #pragma unroll
    for (int k = 0; k < 32; k++) acc = fmaf(fs[nl * 32 + k], w2s[k * 16 + j], acc);
    if (n < NNODES) g_h2[n * 16 + j] = acc;

    float pa = acc * att_src2[j];
    float pb = acc * att_dst2[j];
    #pragma unroll
    for (int off = 1; off <= 8; off <<= 1) {
        pa += __shfl_xor_sync(0xFFFFFFFFu, pa, off);
        pb += __shfl_xor_sync(0xFFFFFFFFu, pb, off);
    }
    if (j == 0 && n < NNODES) { g_as2[n] = pa; g_ad2[n] = pb; }
}

// ---------------- K5: layer2 gather-aggregate + fused edge-MLP precompute -----
// 16-edge batches, prefetched; gather rounds: 8 edges x 4 chunks of 16B.
// Epilogue computes ps/pd (formerly k7a) without materializing out2.
__global__ void k5_csr(const float* __restrict__ b2, const float* __restrict__ Wm1) {
    const int wid  = (blockIdx.x * blockDim.x + threadIdx.x) >> 5;
    const int lane = threadIdx.x & 31;
    if (wid >= NNODES) return;
    const int d   = wid;
    const int beg = g_rowptr[d], end = g_rowptr[d + 1];
    const float ad = g_ad2[d];
    const int sub = lane >> 2, ch = lane & 3;

    float4 acc = make_float4(0.f, 0.f, 0.f, 0.f);
    float den = 0.f;

    // prefetch batch 0 (lanes 0-15 own one edge each)
    bool actp = (lane < 16) && (beg + lane < end);
    int sp = actp ? g_perm[beg + lane].x : 0;
    float asp = actp ? g_as2[sp] : 0.f;

    for (int base = beg; base < end; base += 16) {
        const int  scur = sp;
        const float ascur = asp;
        const bool act = actp;
        int nb = base + 16;
        actp = (lane < 16) && (nb + lane < end);
        sp = actp ? g_perm[nb + lane].x : 0;

        float w = 0.f;
        if (act) {
            float v = ascur + ad;
            v = v > 0.f ? v : NEG_SLOPE * v;
            w = __expf(v);
            den += w;
        }
        #pragma unroll
        for (int r = 0; r < 2; r++) {
            int lsrc = r * 8 + sub;
            int   se = __shfl_sync(0xFFFFFFFFu, scur, lsrc);
            float we = __shfl_sync(0xFFFFFFFFu, w,    lsrc);
            float4 v = *(const float4*)&g_h2[se * 16 + ch * 4];
            acc.x = fmaf(we, v.x, acc.x);
            acc.y = fmaf(we, v.y, acc.y);
            acc.z = fmaf(we, v.z, acc.z);
            acc.w = fmaf(we, v.w, acc.w);
        }
        asp = actp ? g_as2[sp] : 0.f;
    }
    // den total over lanes 0-15
    den += __shfl_xor_sync(0xFFFFFFFFu, den, 1);
    den += __shfl_xor_sync(0xFFFFFFFFu, den, 2);
    den += __shfl_xor_sync(0xFFFFFFFFu, den, 4);
    den += __shfl_xor_sync(0xFFFFFFFFu, den, 8);
    den = __shfl_sync(0xFFFFFFFFu, den, 0);
    // sum acc across the 8 subs (lanes ch, ch+4, ..., ch+28)
    #pragma unroll
    for (int off = 4; off <= 16; off <<= 1) {
        acc.x += __shfl_xor_sync(0xFFFFFFFFu, acc.x, off);
        acc.y += __shfl_xor_sync(0xFFFFFFFFu, acc.y, off);
        acc.z += __shfl_xor_sync(0xFFFFFFFFu, acc.z, off);
        acc.w += __shfl_xor_sync(0xFFFFFFFFu, acc.w, off);
    }
    // g = out2/den + b2   (valid per-lane for its ch; sources lanes 0-3)
    float inv = 1.f / (den + EPS_F);
    float4 b2c = ((const float4*)b2)[ch];
    float4 gg = make_float4(acc.x * inv + b2c.x, acc.y * inv + b2c.y,
                            acc.z * inv + b2c.z, acc.w * inv + b2c.w);
    // broadcast all 16 g values to every lane
    float gv[16];
    #pragma unroll
    for (int c = 0; c < 4; c++) {
        gv[c * 4 + 0] = __shfl_sync(0xFFFFFFFFu, gg.x, c);
        gv[c * 4 + 1] = __shfl_sync(0xFFFFFFFFu, gg.y, c);
        gv[c * 4 + 2] = __shfl_sync(0xFFFFFFFFu, gg.z, c);
        gv[c * 4 + 3] = __shfl_sync(0xFFFFFFFFu, gg.w, c);
    }
    // lanes 0-15: ps[j] = sum_i g[i]*Wm1[i][j]; lanes 16-31: pd[j] (rows 16-31)
    const int half = lane >> 4, j = lane & 15;
    const float* Wcol = Wm1 + half * 256 + j;
    float r = 0.f;
    #pragma unroll
    for (int i = 0; i < 16; i++) r = fmaf(gv[i], Wcol[i * 16], r);
    if (half == 0) g_ps[d * 16 + j] = r;
    else           g_pd[d * 16 + j] = r;
}

// ---------------- K7b: per-edge MLP via CSR (warp per dst node) ---------------
// 16-edge batches, prefetched; rounds: 8 edges x 4 chunks.
__global__ void k7b_csr(const float* __restrict__ bm1, const float* __restrict__ Wm2,
                        const float* __restrict__ bm2, float* __restrict__ out) {
    const int wid  = (blockIdx.x * blockDim.x + threadIdx.x) >> 5;
    const int lane = threadIdx.x & 31;
    if (wid >= NNODES) return;
    const int d   = wid;
    const int beg = g_rowptr[d], end = g_rowptr[d + 1];
    const int sub = lane >> 2, ch = lane & 3;

    float4 pdc = *(const float4*)&g_pd[d * 16 + ch * 4];
    float4 b1c = *(const float4*)&bm1[ch * 4];
    pdc.x += b1c.x; pdc.y += b1c.y; pdc.z += b1c.z; pdc.w += b1c.w;
    float4 w2c = *(const float4*)&Wm2[ch * 4];
    float  bb2 = bm2[0];

    // prefetch batch 0
    bool actp = (lane < 16) && (beg + lane < end);
    int2 pp = actp ? g_perm[beg + lane] : make_int2(0, 0);

    for (int base = beg; base < end; base += 16) {
        const int2 pcur = pp;
        int nb = base + 16;
        actp = (lane < 16) && (nb + lane < end);
        pp = actp ? g_perm[nb + lane] : make_int2(0, 0);

        #pragma unroll
        for (int r = 0; r < 2; r++) {
            int lsrc = r * 8 + sub;
            int se = __shfl_sync(0xFFFFFFFFu, pcur.x, lsrc);
            int oe = __shfl_sync(0xFFFFFFFFu, pcur.y, lsrc);
            float4 p = *(const float4*)&g_ps[se * 16 + ch * 4];
            float h0 = fmaxf(p.x + pdc.x, 0.f);
            float h1 = fmaxf(p.y + pdc.y, 0.f);
            float h2 = fmaxf(p.z + pdc.z, 0.f);
            float h3 = fmaxf(p.w + pdc.w, 0.f);
            float part = h0 * w2c.x + h1 * w2c.y + h2 * w2c.z + h3 * w2c.w;
            part += __shfl_xor_sync(0xFFFFFFFFu, part, 1);
            part += __shfl_xor_sync(0xFFFFFFFFu, part, 2);
            if (ch == 0 && base + r * 8 + sub < end)
                out[oe] = fmaxf(part + bb2, 0.f);
        }
    }
}

// ---------------- launcher ----------------------------------------------------
extern "C" void kernel_launch(void* const* d_in, const int* in_sizes, int n_in,
                              void* d_out, int out_size) {
    const float* x        = (const float*)d_in[0];
    const void*  ei       = d_in[1];
    const float* W1       = (const float*)d_in[2];
    const float* att_src1 = (const float*)d_in[3];
    const float* att_dst1 = (const float*)d_in[4];
    const float* b1       = (const float*)d_in[5];
    const float* W2       = (const float*)d_in[6];
    const float* att_src2 = (const float*)d_in[7];
    const float* att_dst2 = (const float*)d_in[8];
    const float* b2       = (const float*)d_in[9];
    const float* Wm1      = (const float*)d_in[10];
    const float* bm1      = (const float*)d_in[11];
    const float* Wm2      = (const float*)d_in[12];
    const float* bm2      = (const float*)d_in[13];
    float* out = (float*)d_out;

    void* p;
    cudaGetSymbolAddress(&p, g_cnt);
    cudaMemsetAsync(p, 0, (size_t)NNODES * sizeof(int));

    const int smem1 = (8192 + K1_ROWS * K1_PAD) * sizeof(float);
    cudaFuncSetAttribute(k1_gemm, cudaFuncAttributeMaxDynamicSharedMemorySize, smem1);

    const int EB   = (NEDGES + 255) / 256;             // 6250
    const int G1   = (NNODES + K1_ROWS - 1) / K1_ROWS; // 782
    const int NB16 = (NNODES + 15) / 16;               // 3125
    const int NW   = (NNODES * 32 + 255) / 256;        // 6250 (warp-per-node grids)

    kd_detect<<<1, 32>>>((const int*)ei);
    kc_hist<<<EB, 256>>>(ei);
    kc_scan<<<1, 1024>>>();
    kc_scatter<<<EB, 256>>>(ei);
    k1_gemm<<<G1, 128, smem1>>>(x, W1, att_src1, att_dst1);
    k2_csr<<<NW, 256>>>();
    k4_gemm2<<<NB16, 256>>>(b1, W2, att_src2, att_dst2);
    k5_csr<<<NW, 256>>>(b2, Wm1);
    k7b_csr<<<NW, 256>>>(bm1, Wm2, bm2, out);
    (void)in_sizes; (void)n_in; (void)out_size;
}

// round 12
// speedup vs baseline: 2.7630x; 1.3260x over previous
#include <cuda_runtime.h>
#include <cuda_bf16.h>
#include <math.h>

#define NNODES 50000
#define NEDGES 1600000
#define NEG_SLOPE 0.2f
#define EPS_F 1e-16f

// ---------------- scratch (device globals) ------------------------------------
__device__ __align__(16) float g_h1[NNODES * 32];   // layer1 linear output [N,2,16]
__device__ __align__(16) float g_as1[NNODES * 2];
__device__ __align__(16) float g_ad1[NNODES * 2];
__device__ __align__(16) float g_out1[NNODES * 32]; // NORMALIZED aggregate, layer1
__device__ __align__(16) float g_h2[NNODES * 16];
__device__ __align__(16) float g_as2[NNODES];
__device__ __align__(16) float g_ad2[NNODES];
__device__ __align__(16) float g_ps[NNODES * 16];
__device__ __align__(16) float g_pd[NNODES * 16];
__device__ __align__(16) int2  g_perm[NEDGES];      // CSR payload: {src, orig_edge}
__device__ __align__(16) int2  g_sd[NEDGES];        // staged {src, dst}
__device__ __align__(16) int   g_rank[NEDGES];      // rank of edge within its dst row
__device__ __align__(16) int   g_rowptr[NNODES + 1];
__device__ __align__(16) int   g_cnt[NNODES];       // histogram
__device__ int g_is64;

// ---------------- Kd: detect int64 vs int32 edge_index layout ----------------
__global__ void kd_detect(const int* __restrict__ ei32) {
    if (threadIdx.x == 0 && blockIdx.x == 0) {
        int any = 0;
        #pragma unroll 8
        for (int i = 1; i < 2048; i += 2) any |= ei32[i];
        g_is64 = (any == 0) ? 1 : 0;
    }
}

__device__ __forceinline__ int dec_idx(const void* ei, int pos) {
    int v;
    if (g_is64) v = (int)((const long long*)ei)[pos];
    else        v = ((const int*)ei)[pos];
    return min(max(v, 0), NNODES - 1);
}

// ---------------- CSR build: hist(+rank) -> scan -> atomic-free scatter -------
__global__ void kc_hist(const void* __restrict__ ei) {
    int e = blockIdx.x * blockDim.x + threadIdx.x;
    if (e >= NEDGES) return;
    int s = dec_idx(ei, e);
    int d = dec_idx(ei, NEDGES + e);
    int r = atomicAdd(&g_cnt[d], 1);
    g_sd[e] = make_int2(s, d);
    g_rank[e] = r;
}

__global__ void kc_scan(void) {
    __shared__ int sums[1024];
    const int t = threadIdx.x;
    const int CH = 49;                       // 1024*49 = 50176 >= 50000
    int lo = t * CH, hi = min(lo + CH, NNODES);
    int s = 0;
    for (int i = lo; i < hi; i++) s += g_cnt[i];
    sums[t] = s;
    __syncthreads();
    for (int off = 1; off < 1024; off <<= 1) {
        int v = (t >= off) ? sums[t - off] : 0;
        __syncthreads();
        sums[t] += v;
        __syncthreads();
    }
    int run = (t > 0) ? sums[t - 1] : 0;
    for (int i = lo; i < hi; i++) {
        int c = g_cnt[i];
        g_rowptr[i] = run;
        run += c;
    }
    if (t == 1023) g_rowptr[NNODES] = run;
}

__global__ void kc_scatter(void) {
    int e = blockIdx.x * blockDim.x + threadIdx.x;
    if (e >= NEDGES) return;
    int2 sd = g_sd[e];
    int pos = g_rowptr[sd.y] + g_rank[e];
    g_perm[pos] = make_int2(sd.x, e);
}

// ---------------- K1: h1 = x @ W1, plus attention logits ---------------------
#define K1_ROWS 64
#define K1_PAD  258

__global__ void k1_gemm(const float* __restrict__ x, const float* __restrict__ W1,
                        const float* __restrict__ att_src1, const float* __restrict__ att_dst1) {
    extern __shared__ float sm[];
    float* ws = sm;                 // 256*32 floats
    float* xs = sm + 8192;          // 64 * 258 floats

    const int t = threadIdx.x;      // 0..127
    const int n0 = blockIdx.x * K1_ROWS;

    const float4* W4 = (const float4*)W1;
    for (int i = t; i < 2048; i += 128) ((float4*)ws)[i] = W4[i];

    for (int i = t; i < K1_ROWS * 64; i += 128) {
        int r = i >> 6;
        int q = i & 63;
        int n = n0 + r;
        float4 v = make_float4(0.f, 0.f, 0.f, 0.f);
        if (n < NNODES) v = ((const float4*)x)[(size_t)n * 64 + q];
        float* d = &xs[r * K1_PAD + (q << 2)];
        d[0] = v.x; d[1] = v.y; d[2] = v.z; d[3] = v.w;
    }
    __syncthreads();

    const int tc = t & 7;
    const int tr = t >> 3;
    const int c0 = tc * 4;
    const int r0 = tr * 4;

    float acc[4][4] = {};
    #pragma unroll 4
    for (int k = 0; k < 256; k++) {
        float4 w = *(const float4*)&ws[k * 32 + c0];
        #pragma unroll
        for (int i = 0; i < 4; i++) {
            float xv = xs[(r0 + i) * K1_PAD + k];
            acc[i][0] = fmaf(xv, w.x, acc[i][0]);
            acc[i][1] = fmaf(xv, w.y, acc[i][1]);
            acc[i][2] = fmaf(xv, w.z, acc[i][2]);
            acc[i][3] = fmaf(xv, w.w, acc[i][3]);
        }
    }

    float4 sA = ((const float4*)att_src1)[tc];
    float4 dA = ((const float4*)att_dst1)[tc];
    float pas[4], pad_[4];
    #pragma unroll
    for (int i = 0; i < 4; i++) {
        pas[i]  = acc[i][0]*sA.x + acc[i][1]*sA.y + acc[i][2]*sA.z + acc[i][3]*sA.w;
        pad_[i] = acc[i][0]*dA.x + acc[i][1]*dA.y + acc[i][2]*dA.z + acc[i][3]*dA.w;
    }
    #pragma unroll
    for (int off = 1; off <= 2; off <<= 1) {
        #pragma unroll
        for (int i = 0; i < 4; i++) {
            pas[i]  += __shfl_xor_sync(0xFFFFFFFFu, pas[i],  off);
            pad_[i] += __shfl_xor_sync(0xFFFFFFFFu, pad_[i], off);
        }
    }
    if ((tc & 3) == 0) {
        int h = tc >> 2;
        #pragma unroll
        for (int i = 0; i < 4; i++) {
            int n = n0 + r0 + i;
            if (n < NNODES) {
                g_as1[n * 2 + h] = pas[i];
                g_ad1[n * 2 + h] = pad_[i];
            }
        }
    }
    #pragma unroll
    for (int i = 0; i < 4; i++) {
        int n = n0 + r0 + i;
        if (n < NNODES)
            *(float4*)&g_h1[n * 32 + c0] = make_float4(acc[i][0], acc[i][1], acc[i][2], acc[i][3]);
    }
}

// ---------------- K2: layer1 gather-aggregate (warp per dst node) -------------
// 8-edge batches, prefetched; gather rounds: 4 edges x 8 chunks of 16B.
__global__ void k2_csr(void) {
    const int wid  = (blockIdx.x * blockDim.x + threadIdx.x) >> 5;
    const int lane = threadIdx.x & 31;
    if (wid >= NNODES) return;
    const int d   = wid;
    const int beg = g_rowptr[d], end = g_rowptr[d + 1];
    const float2 ad = *(const float2*)&g_ad1[d * 2];
    const int sub = lane >> 3, ch = lane & 7;

    float4 acc = make_float4(0.f, 0.f, 0.f, 0.f);
    float den0 = 0.f, den1 = 0.f;

    bool actp = (lane < 8) && (beg + lane < end);
    int sp = actp ? g_perm[beg + lane].x : 0;
    float2 asp = actp ? *(const float2*)&g_as1[sp * 2] : make_float2(0.f, 0.f);

    for (int base = beg; base < end; base += 8) {
        const int  scur = sp;
        const float2 ascur = asp;
        const bool act = actp;
        int nb = base + 8;
        actp = (lane < 8) && (nb + lane < end);
        sp = actp ? g_perm[nb + lane].x : 0;

        float w0 = 0.f, w1 = 0.f;
        if (act) {
            float v0 = ascur.x + ad.x; v0 = v0 > 0.f ? v0 : NEG_SLOPE * v0;
            float v1 = ascur.y + ad.y; v1 = v1 > 0.f ? v1 : NEG_SLOPE * v1;
            w0 = __expf(v0); w1 = __expf(v1);
            den0 += w0; den1 += w1;
        }
        #pragma unroll
        for (int r = 0; r < 2; r++) {
            int lsrc = r * 4 + sub;
            int   se  = __shfl_sync(0xFFFFFFFFu, scur, lsrc);
            float w0e = __shfl_sync(0xFFFFFFFFu, w0,   lsrc);
            float w1e = __shfl_sync(0xFFFFFFFFu, w1,   lsrc);
            float we = (ch < 4) ? w0e : w1e;
            float4 v = *(const float4*)&g_h1[se * 32 + ch * 4];
            acc.x = fmaf(we, v.x, acc.x);
            acc.y = fmaf(we, v.y, acc.y);
            acc.z = fmaf(we, v.z, acc.z);
            acc.w = fmaf(we, v.w, acc.w);
        }
        asp = actp ? *(const float2*)&g_as1[sp * 2] : make_float2(0.f, 0.f);
    }
    den0 += __shfl_xor_sync(0xFFFFFFFFu, den0, 1);
    den0 += __shfl_xor_sync(0xFFFFFFFFu, den0, 2);
    den0 += __shfl_xor_sync(0xFFFFFFFFu, den0, 4);
    den1 += __shfl_xor_sync(0xFFFFFFFFu, den1, 1);
    den1 += __shfl_xor_sync(0xFFFFFFFFu, den1, 2);
    den1 += __shfl_xor_sync(0xFFFFFFFFu, den1, 4);
    den0 = __shfl_sync(0xFFFFFFFFu, den0, 0);
    den1 = __shfl_sync(0xFFFFFFFFu, den1, 0);
    #pragma unroll
    for (int off = 8; off <= 16; off <<= 1) {
        acc.x += __shfl_xor_sync(0xFFFFFFFFu, acc.x, off);
        acc.y += __shfl_xor_sync(0xFFFFFFFFu, acc.y, off);
        acc.z += __shfl_xor_sync(0xFFFFFFFFu, acc.z, off);
        acc.w += __shfl_xor_sync(0xFFFFFFFFu, acc.w, off);
    }
    if (lane < 8) {
        float dn = ((lane < 4) ? den0 : den1) + EPS_F;
        float inv = 1.f / dn;
        *(float4*)&g_out1[d * 32 + lane * 4] =
            make_float4(acc.x * inv, acc.y * inv, acc.z * inv, acc.w * inv);
    }
}

// ---------------- K4: elu(out1+b1) @ W2, layer2 logits -----------------------
__global__ void k4_gemm2(const float* __restrict__ b1, const float* __restrict__ W2,
                         const float* __restrict__ att_src2, const float* __restrict__ att_dst2) {
    __shared__ float w2s[512];
    __shared__ float fs[512];
    const int t = threadIdx.x;      // 256 threads, 16 nodes/block
    const int n0 = blockIdx.x * 16;

    for (int i = t; i < 512; i += 256) w2s[i] = W2[i];
    for (int i = t; i < 512; i += 256) {
        size_t lin = (size_t)n0 * 32 + i;
        float v = (lin < (size_t)NNODES * 32) ? (g_out1[lin] + b1[i & 31]) : 0.f;
        fs[i] = v > 0.f ? v : (__expf(v) - 1.f);   // elu
    }
    __syncthreads();

    const int nl = t >> 4, j = t & 15;
    const int n = n0 + nl;
    float acc = 0.f;
    #pragma unroll
    for (int k = 0; k < 32; k++) acc = fmaf(fs[nl * 32 + k], w2s[k * 16 + j], acc);
    if (n < NNODES) g_h2[n * 16 + j] = acc;

    float pa = acc * att_src2[j];
    float pb = acc * att_dst2[j];
    #pragma unroll
    for (int off = 1; off <= 8; off <<= 1) {
        pa += __shfl_xor_sync(0xFFFFFFFFu, pa, off);
        pb += __shfl_xor_sync(0xFFFFFFFFu, pb, off);
    }
    if (j == 0 && n < NNODES) { g_as2[n] = pa; g_ad2[n] = pb; }
}

// ---------------- K5: layer2 gather-aggregate + fused edge-MLP precompute -----
__global__ void k5_csr(const float* __restrict__ b2, const float* __restrict__ Wm1) {
    const int wid  = (blockIdx.x * blockDim.x + threadIdx.x) >> 5;
    const int lane = threadIdx.x & 31;
    if (wid >= NNODES) return;
    const int d   = wid;
    const int beg = g_rowptr[d], end = g_rowptr[d + 1];
    const float ad = g_ad2[d];
    const int sub = lane >> 2, ch = lane & 3;

    float4 acc = make_float4(0.f, 0.f, 0.f, 0.f);
    float den = 0.f;

    bool actp = (lane < 16) && (beg + lane < end);
    int sp = actp ? g_perm[beg + lane].x : 0;
    float asp = actp ? g_as2[sp] : 0.f;

    for (int base = beg; base < end; base += 16) {
        const int  scur = sp;
        const float ascur = asp;
        const bool act = actp;
        int nb = base + 16;
        actp = (lane < 16) && (nb + lane < end);
        sp = actp ? g_perm[nb + lane].x : 0;

        float w = 0.f;
        if (act) {
            float v = ascur + ad;
            v = v > 0.f ? v : NEG_SLOPE * v;
            w = __expf(v);
            den += w;
        }
        #pragma unroll
        for (int r = 0; r < 2; r++) {
            int lsrc = r * 8 + sub;
            int   se = __shfl_sync(0xFFFFFFFFu, scur, lsrc);
            float we = __shfl_sync(0xFFFFFFFFu, w,    lsrc);
            float4 v = *(const float4*)&g_h2[se * 16 + ch * 4];
            acc.x = fmaf(we, v.x, acc.x);
            acc.y = fmaf(we, v.y, acc.y);
            acc.z = fmaf(we, v.z, acc.z);
            acc.w = fmaf(we, v.w, acc.w);
        }
        asp = actp ? g_as2[sp] : 0.f;
    }
    den += __shfl_xor_sync(0xFFFFFFFFu, den, 1);
    den += __shfl_xor_sync(0xFFFFFFFFu, den, 2);
    den += __shfl_xor_sync(0xFFFFFFFFu, den, 4);
    den += __shfl_xor_sync(0xFFFFFFFFu, den, 8);
    den = __shfl_sync(0xFFFFFFFFu, den, 0);
    #pragma unroll
    for (int off = 4; off <= 16; off <<= 1) {
        acc.x += __shfl_xor_sync(0xFFFFFFFFu, acc.x, off);
        acc.y += __shfl_xor_sync(0xFFFFFFFFu, acc.y, off);
        acc.z += __shfl_xor_sync(0xFFFFFFFFu, acc.z, off);
        acc.w += __shfl_xor_sync(0xFFFFFFFFu, acc.w, off);
    }
    float inv = 1.f / (den + EPS_F);
    float4 b2c = ((const float4*)b2)[ch];
    float4 gg = make_float4(acc.x * inv + b2c.x, acc.y * inv + b2c.y,
                            acc.z * inv + b2c.z, acc.w * inv + b2c.w);
    float gv[16];
    #pragma unroll
    for (int c = 0; c < 4; c++) {
        gv[c * 4 + 0] = __shfl_sync(0xFFFFFFFFu, gg.x, c);
        gv[c * 4 + 1] = __shfl_sync(0xFFFFFFFFu, gg.y, c);
        gv[c * 4 + 2] = __shfl_sync(0xFFFFFFFFu, gg.z, c);
        gv[c * 4 + 3] = __shfl_sync(0xFFFFFFFFu, gg.w, c);
    }
    const int half = lane >> 4, j = lane & 15;
    const float* Wcol = Wm1 + half * 256 + j;
    float r = 0.f;
    #pragma unroll
    for (int i = 0; i < 16; i++) r = fmaf(gv[i], Wcol[i * 16], r);
    if (half == 0) g_ps[d * 16 + j] = r;
    else           g_pd[d * 16 + j] = r;
}

// ---------------- K7b: per-edge MLP via CSR (warp per dst node) ---------------
__global__ void k7b_csr(const float* __restrict__ bm1, const float* __restrict__ Wm2,
                        const float* __restrict__ bm2, float* __restrict__ out) {
    const int wid  = (blockIdx.x * blockDim.x + threadIdx.x) >> 5;
    const int lane = threadIdx.x & 31;
    if (wid >= NNODES) return;
    const int d   = wid;
    const int beg = g_rowptr[d], end = g_rowptr[d + 1];
    const int sub = lane >> 2, ch = lane & 3;

    float4 pdc = *(const float4*)&g_pd[d * 16 + ch * 4];
    float4 b1c = *(const float4*)&bm1[ch * 4];
    pdc.x += b1c.x; pdc.y += b1c.y; pdc.z += b1c.z; pdc.w += b1c.w;
    float4 w2c = *(const float4*)&Wm2[ch * 4];
    float  bb2 = bm2[0];

    bool actp = (lane < 16) && (beg + lane < end);
    int2 pp = actp ? g_perm[beg + lane] : make_int2(0, 0);

    for (int base = beg; base < end; base += 16) {
        const int2 pcur = pp;
        int nb = base + 16;
        actp = (lane < 16) && (nb + lane < end);
        pp = actp ? g_perm[nb + lane] : make_int2(0, 0);

        #pragma unroll
        for (int r = 0; r < 2; r++) {
            int lsrc = r * 8 + sub;
            int se = __shfl_sync(0xFFFFFFFFu, pcur.x, lsrc);
            int oe = __shfl_sync(0xFFFFFFFFu, pcur.y, lsrc);
            float4 p = *(const float4*)&g_ps[se * 16 + ch * 4];
            float h0 = fmaxf(p.x + pdc.x, 0.f);
            float h1 = fmaxf(p.y + pdc.y, 0.f);
            float h2 = fmaxf(p.z + pdc.z, 0.f);
            float h3 = fmaxf(p.w + pdc.w, 0.f);
            float part = h0 * w2c.x + h1 * w2c.y + h2 * w2c.z + h3 * w2c.w;
            part += __shfl_xor_sync(0xFFFFFFFFu, part, 1);
            part += __shfl_xor_sync(0xFFFFFFFFu, part, 2);
            if (ch == 0 && base + r * 8 + sub < end)
                out[oe] = fmaxf(part + bb2, 0.f);
        }
    }
}

// ---------------- launcher ----------------------------------------------------
extern "C" void kernel_launch(void* const* d_in, const int* in_sizes, int n_in,
                              void* d_out, int out_size) {
    const float* x        = (const float*)d_in[0];
    const void*  ei       = d_in[1];
    const float* W1       = (const float*)d_in[2];
    const float* att_src1 = (const float*)d_in[3];
    const float* att_dst1 = (const float*)d_in[4];
    const float* b1       = (const float*)d_in[5];
    const float* W2       = (const float*)d_in[6];
    const float* att_src2 = (const float*)d_in[7];
    const float* att_dst2 = (const float*)d_in[8];
    const float* b2       = (const float*)d_in[9];
    const float* Wm1      = (const float*)d_in[10];
    const float* bm1      = (const float*)d_in[11];
    const float* Wm2      = (const float*)d_in[12];
    const float* bm2      = (const float*)d_in[13];
    float* out = (float*)d_out;

    // side stream + fork/join events; created on the first (uncaptured)
    // correctness call, reused by the capture call.
    static cudaStream_t s2 = nullptr;
    static cudaEvent_t evF = nullptr, evJ = nullptr;
    if (s2 == nullptr) {
        cudaStreamCreateWithFlags(&s2, cudaStreamNonBlocking);
        cudaEventCreateWithFlags(&evF, cudaEventDisableTiming);
        cudaEventCreateWithFlags(&evJ, cudaEventDisableTiming);
    }

    void* pcnt;
    cudaGetSymbolAddress(&pcnt, g_cnt);

    const int smem1 = (8192 + K1_ROWS * K1_PAD) * sizeof(float);
    cudaFuncSetAttribute(k1_gemm, cudaFuncAttributeMaxDynamicSharedMemorySize, smem1);

    const int EB   = (NEDGES + 255) / 256;             // 6250
    const int G1   = (NNODES + K1_ROWS - 1) / K1_ROWS; // 782
    const int NB16 = (NNODES + 15) / 16;               // 3125
    const int NW   = (NNODES * 32 + 255) / 256;        // 6250 (warp-per-node grids)

    // fork: CSR build on s2, GEMM1 on main stream
    cudaEventRecord(evF, 0);
    cudaStreamWaitEvent(s2, evF, 0);

    cudaMemsetAsync(pcnt, 0, (size_t)NNODES * sizeof(int), s2);
    kd_detect<<<1, 32, 0, s2>>>((const int*)ei);
    kc_hist<<<EB, 256, 0, s2>>>(ei);
    kc_scan<<<1, 1024, 0, s2>>>();
    kc_scatter<<<EB, 256, 0, s2>>>();
    cudaEventRecord(evJ, s2);

    k1_gemm<<<G1, 128, smem1>>>(x, W1, att_src1, att_dst1);

    // join: everything below needs both branches
    cudaStreamWaitEvent(0, evJ, 0);

    k2_csr<<<NW, 256>>>();
    k4_gemm2<<<NB16, 256>>>(b1, W2, att_src2, att_dst2);
    k5_csr<<<NW, 256>>>(b2, Wm1);
    k7b_csr<<<NW, 256>>>(bm1, Wm2, bm2, out);
    (void)in_sizes; (void)n_in; (void)out_size;
}